// round 1
// baseline (speedup 1.0000x reference)
#include <cuda_runtime.h>

// Problem constants (fixed-shape problem)
#define NN 50000
#define HH 128
#define EE 800000
#define AA 16
#define TT 4
#define HA 144            // H + A
#define TILE_E 64
#define XS_STRIDE 65      // padded row stride for transposed x/hidden tiles

// ---------------- device scratch (no allocations allowed) ----------------
__device__ float g_msg[NN * HH];          // scatter-add target [N,H]
__device__ int   g_bucket[EE];            // edge ids sorted by type
__device__ int   g_cnt[TT];
__device__ int   g_cur[TT];
__device__ int   g_off[TT + 1];
__device__ int   g_tileBase[TT + 1];
__device__ float g_wihT[HH * 3 * HH];     // w_ih transposed to [k][gate]
__device__ float g_whhT[HH * 3 * HH];

// ---------------- utility kernels ----------------
__global__ void k_zero() {
    int idx = blockIdx.x * blockDim.x + threadIdx.x;
    int stride = gridDim.x * blockDim.x;
    float4* p = reinterpret_cast<float4*>(g_msg);
    int total4 = NN * HH / 4;
    float4 z = make_float4(0.f, 0.f, 0.f, 0.f);
    for (int i = idx; i < total4; i += stride) p[i] = z;
    if (idx < TT) g_cnt[idx] = 0;
}

__global__ void k_transpose(const float* __restrict__ wih,
                            const float* __restrict__ whh) {
    int idx = blockIdx.x * blockDim.x + threadIdx.x;
    if (idx < HH * 3 * HH) {
        int k = idx / (3 * HH);
        int g = idx % (3 * HH);
        g_wihT[idx] = wih[g * HH + k];
        g_whhT[idx] = whh[g * HH + k];
    }
}

__global__ void k_hist(const int* __restrict__ et, int E) {
    __shared__ int c[TT];
    if (threadIdx.x < TT) c[threadIdx.x] = 0;
    __syncthreads();
    int i = blockIdx.x * blockDim.x + threadIdx.x;
    if (i < E) atomicAdd(&c[et[i]], 1);
    __syncthreads();
    if (threadIdx.x < TT && c[threadIdx.x] > 0)
        atomicAdd(&g_cnt[threadIdx.x], c[threadIdx.x]);
}

__global__ void k_scan() {
    int off = 0, tb = 0;
    for (int t = 0; t < TT; t++) {
        g_off[t] = off;
        g_cur[t] = off;
        g_tileBase[t] = tb;
        tb += (g_cnt[t] + TILE_E - 1) / TILE_E;
        off += g_cnt[t];
    }
    g_off[TT] = off;
    g_tileBase[TT] = tb;
}

__global__ void k_scatter(const int* __restrict__ et, int E) {
    __shared__ int c[TT], base[TT];
    if (threadIdx.x < TT) c[threadIdx.x] = 0;
    __syncthreads();
    int i = blockIdx.x * blockDim.x + threadIdx.x;
    int t = 0, pos = 0;
    bool valid = (i < E);
    if (valid) {
        t = et[i];
        pos = atomicAdd(&c[t], 1);
    }
    __syncthreads();
    if (threadIdx.x < TT)
        base[threadIdx.x] = (c[threadIdx.x] > 0)
            ? atomicAdd(&g_cur[threadIdx.x], c[threadIdx.x]) : 0;
    __syncthreads();
    if (valid) g_bucket[base[t] + pos] = i;
}

// ---------------- edge MLP + scatter-add ----------------
// CTA = 64 edges of one type. 256 threads; thread = 8 edges x 4 cols.
__global__ __launch_bounds__(256)
void k_mlp(const float* __restrict__ h,
           const int*   __restrict__ ei,     // [2,E]
           const float* __restrict__ ea,     // [E,A]
           const float* __restrict__ W1,     // [T,144,128]
           const float* __restrict__ b1,     // [T,128]
           const float* __restrict__ W2,     // [T,128,128]
           const float* __restrict__ b2,     // [T,128]
           int E) {
    __shared__ __align__(16) float s_x[HA * XS_STRIDE];   // x tile, later hidden tile
    __shared__ __align__(16) float ws[16 * HH];           // weight k-tile
    __shared__ int s_dst[TILE_E];
    __shared__ int s_src[TILE_E];
    __shared__ int s_eid[TILE_E];

    // which type / segment does this block own?
    int tb0 = g_tileBase[0], tb1 = g_tileBase[1], tb2 = g_tileBase[2],
        tb3 = g_tileBase[3], tb4 = g_tileBase[4];
    int b = blockIdx.x;
    if (b >= tb4) return;
    int t;
    if      (b < tb1) t = 0;
    else if (b < tb2) t = 1;
    else if (b < tb3) t = 2;
    else              t = 3;
    int tbt = (t == 0) ? tb0 : (t == 1) ? tb1 : (t == 2) ? tb2 : tb3;
    int localTile = b - tbt;
    int segBase = g_off[t] + localTile * TILE_E;
    int segCnt  = g_off[t + 1] - segBase;
    if (segCnt > TILE_E) segCnt = TILE_E;
    if (segCnt <= 0) return;

    const int* srcp = ei;
    const int* dstp = ei + E;

    // load edge metadata
    for (int i = threadIdx.x; i < TILE_E; i += 256) {
        if (i < segCnt) {
            int e = g_bucket[segBase + i];
            s_eid[i] = e;
            s_src[i] = srcp[e];
            s_dst[i] = dstp[e];
        } else {
            s_eid[i] = 0; s_src[i] = 0; s_dst[i] = -1;
        }
    }
    __syncthreads();

    // gather x transposed: s_x[j][i], warp-per-edge, conflict-free stride 65
    {
        int warp = threadIdx.x >> 5, lane = threadIdx.x & 31;
        for (int i = warp; i < TILE_E; i += 8) {
            int sidx = s_src[i];
            int e = s_eid[i];
            bool valid = (i < segCnt);
            for (int j = lane; j < HA; j += 32) {
                float v = 0.f;
                if (valid)
                    v = (j < HH) ? h[sidx * HH + j] : ea[e * AA + (j - HH)];
                s_x[j * XS_STRIDE + i] = v;
            }
        }
    }

    int tx = threadIdx.x & 31;   // 4 cols:  tx*4 .. tx*4+3
    int ty = threadIdx.x >> 5;   // 8 edges: ty*8 .. ty*8+7

    float acc[8][4];
    #pragma unroll
    for (int r = 0; r < 8; r++)
        #pragma unroll
        for (int c = 0; c < 4; c++) acc[r][c] = 0.f;

    // ---- GEMM1: hidden = relu(X @ W1[t] + b1[t]),  K = 144 ----
    const float* W1t = W1 + t * HA * HH;
    for (int k0 = 0; k0 < HA; k0 += 16) {
        __syncthreads();
        for (int i = threadIdx.x; i < 16 * HH; i += 256)
            ws[i] = W1t[k0 * HH + i];
        __syncthreads();
        #pragma unroll
        for (int kk = 0; kk < 16; kk++) {
            const float* xrow = &s_x[(k0 + kk) * XS_STRIDE + ty * 8];
            float4 w = *(const float4*)&ws[kk * HH + tx * 4];
            #pragma unroll
            for (int r = 0; r < 8; r++) {
                float xv = xrow[r];
                acc[r][0] += xv * w.x;
                acc[r][1] += xv * w.y;
                acc[r][2] += xv * w.z;
                acc[r][3] += xv * w.w;
            }
        }
    }

    // epilogue 1: relu + bias, store hidden transposed into s_x (x is dead)
    float4 b1v = *(const float4*)&b1[t * HH + tx * 4];
    __syncthreads();
    #pragma unroll
    for (int r = 0; r < 8; r++) {
        s_x[(tx * 4 + 0) * XS_STRIDE + ty * 8 + r] = fmaxf(acc[r][0] + b1v.x, 0.f);
        s_x[(tx * 4 + 1) * XS_STRIDE + ty * 8 + r] = fmaxf(acc[r][1] + b1v.y, 0.f);
        s_x[(tx * 4 + 2) * XS_STRIDE + ty * 8 + r] = fmaxf(acc[r][2] + b1v.z, 0.f);
        s_x[(tx * 4 + 3) * XS_STRIDE + ty * 8 + r] = fmaxf(acc[r][3] + b1v.w, 0.f);
    }
    __syncthreads();

    #pragma unroll
    for (int r = 0; r < 8; r++)
        #pragma unroll
        for (int c = 0; c < 4; c++) acc[r][c] = 0.f;

    // ---- GEMM2: m = hidden @ W2[t] + b2[t],  K = 128 ----
    const float* W2t = W2 + t * HH * HH;
    for (int k0 = 0; k0 < HH; k0 += 16) {
        __syncthreads();
        for (int i = threadIdx.x; i < 16 * HH; i += 256)
            ws[i] = W2t[k0 * HH + i];
        __syncthreads();
        #pragma unroll
        for (int kk = 0; kk < 16; kk++) {
            const float* xrow = &s_x[(k0 + kk) * XS_STRIDE + ty * 8];
            float4 w = *(const float4*)&ws[kk * HH + tx * 4];
            #pragma unroll
            for (int r = 0; r < 8; r++) {
                float xv = xrow[r];
                acc[r][0] += xv * w.x;
                acc[r][1] += xv * w.y;
                acc[r][2] += xv * w.z;
                acc[r][3] += xv * w.w;
            }
        }
    }

    // epilogue 2: bias + scatter-add to g_msg
    float4 b2v = *(const float4*)&b2[t * HH + tx * 4];
    #pragma unroll
    for (int r = 0; r < 8; r++) {
        int d = s_dst[ty * 8 + r];
        if (d >= 0) {
            float* mp = &g_msg[d * HH + tx * 4];
            atomicAdd(mp + 0, acc[r][0] + b2v.x);
            atomicAdd(mp + 1, acc[r][1] + b2v.y);
            atomicAdd(mp + 2, acc[r][2] + b2v.z);
            atomicAdd(mp + 3, acc[r][3] + b2v.w);
        }
    }
}

// ---------------- fused GRU cell ----------------
// CTA = 16 nodes, 256 threads; thread = 2 nodes x 4 j-cols x 4 planes (r,z,i_n,h_n)
__global__ __launch_bounds__(256)
void k_gru(const float* __restrict__ h,
           const float* __restrict__ b_ih,
           const float* __restrict__ b_hh,
           float* __restrict__ out, int N) {
    __shared__ __align__(16) float s_ms[HH * 16];
    __shared__ __align__(16) float s_h [HH * 16];
    __shared__ __align__(16) float s_wi[8 * 3 * HH];
    __shared__ __align__(16) float s_wh[8 * 3 * HH];
    __shared__ float s_bih[3 * HH];
    __shared__ float s_bhh[3 * HH];

    int n0 = blockIdx.x * 16;
    for (int i = threadIdx.x; i < 3 * HH; i += 256) {
        s_bih[i] = b_ih[i];
        s_bhh[i] = b_hh[i];
    }
    for (int idx = threadIdx.x; idx < 16 * HH; idx += 256) {
        int i = idx / HH, k = idx % HH;
        int n = n0 + i;
        float mv = 0.f, hv = 0.f;
        if (n < N) { mv = g_msg[n * HH + k]; hv = h[n * HH + k]; }
        s_ms[k * 16 + i] = mv;
        s_h [k * 16 + i] = hv;
    }

    int tx = threadIdx.x & 31;   // j = tx*4
    int ty = threadIdx.x >> 5;   // nodes ty*2, ty*2+1
    int j = tx * 4;
    int nb = ty * 2;

    float sr[2][4], sz[2][4], si[2][4], sh[2][4];
    #pragma unroll
    for (int i = 0; i < 2; i++)
        #pragma unroll
        for (int c = 0; c < 4; c++) { sr[i][c] = 0.f; sz[i][c] = 0.f; si[i][c] = 0.f; sh[i][c] = 0.f; }

    for (int k0 = 0; k0 < HH; k0 += 8) {
        __syncthreads();
        for (int idx = threadIdx.x; idx < 8 * 3 * HH; idx += 256) {
            s_wi[idx] = g_wihT[k0 * 3 * HH + idx];
            s_wh[idx] = g_whhT[k0 * 3 * HH + idx];
        }
        __syncthreads();
        #pragma unroll
        for (int kk = 0; kk < 8; kk++) {
            float m0 = s_ms[(k0 + kk) * 16 + nb];
            float m1 = s_ms[(k0 + kk) * 16 + nb + 1];
            float h0 = s_h [(k0 + kk) * 16 + nb];
            float h1 = s_h [(k0 + kk) * 16 + nb + 1];
            float wir[4], wiz[4], win[4], whr[4], whz[4], whn[4];
            {
                float4 a = *(const float4*)&s_wi[kk * 3 * HH + j];
                float4 bq = *(const float4*)&s_wi[kk * 3 * HH + 128 + j];
                float4 cq = *(const float4*)&s_wi[kk * 3 * HH + 256 + j];
                wir[0]=a.x; wir[1]=a.y; wir[2]=a.z; wir[3]=a.w;
                wiz[0]=bq.x; wiz[1]=bq.y; wiz[2]=bq.z; wiz[3]=bq.w;
                win[0]=cq.x; win[1]=cq.y; win[2]=cq.z; win[3]=cq.w;
                float4 d = *(const float4*)&s_wh[kk * 3 * HH + j];
                float4 e = *(const float4*)&s_wh[kk * 3 * HH + 128 + j];
                float4 f = *(const float4*)&s_wh[kk * 3 * HH + 256 + j];
                whr[0]=d.x; whr[1]=d.y; whr[2]=d.z; whr[3]=d.w;
                whz[0]=e.x; whz[1]=e.y; whz[2]=e.z; whz[3]=e.w;
                whn[0]=f.x; whn[1]=f.y; whn[2]=f.z; whn[3]=f.w;
            }
            #pragma unroll
            for (int c = 0; c < 4; c++) {
                sr[0][c] += m0 * wir[c] + h0 * whr[c];
                sr[1][c] += m1 * wir[c] + h1 * whr[c];
                sz[0][c] += m0 * wiz[c] + h0 * whz[c];
                sz[1][c] += m1 * wiz[c] + h1 * whz[c];
                si[0][c] += m0 * win[c];
                si[1][c] += m1 * win[c];
                sh[0][c] += h0 * whn[c];
                sh[1][c] += h1 * whn[c];
            }
        }
    }

    #pragma unroll
    for (int i = 0; i < 2; i++) {
        int n = n0 + nb + i;
        if (n >= N) continue;
        float o[4];
        #pragma unroll
        for (int c = 0; c < 4; c++) {
            int jc = j + c;
            float rg = sr[i][c] + s_bih[jc] + s_bhh[jc];
            rg = 1.f / (1.f + __expf(-rg));
            float zg = sz[i][c] + s_bih[128 + jc] + s_bhh[128 + jc];
            zg = 1.f / (1.f + __expf(-zg));
            float ing = si[i][c] + s_bih[256 + jc];
            float hng = sh[i][c] + s_bhh[256 + jc];
            float ng = tanhf(ing + rg * hng);
            float hv = s_h[jc * 16 + nb + i];
            o[c] = (1.f - zg) * ng + zg * hv;
        }
        *(float4*)&out[n * HH + j] = make_float4(o[0], o[1], o[2], o[3]);
    }
}

// ---------------- launch ----------------
extern "C" void kernel_launch(void* const* d_in, const int* in_sizes, int n_in,
                              void* d_out, int out_size) {
    const float* h    = (const float*)d_in[0];
    const int*   ei   = (const int*)  d_in[1];
    const int*   et   = (const int*)  d_in[2];
    const float* ea   = (const float*)d_in[3];
    const float* W1   = (const float*)d_in[4];
    const float* b1   = (const float*)d_in[5];
    const float* W2   = (const float*)d_in[6];
    const float* b2   = (const float*)d_in[7];
    const float* wih  = (const float*)d_in[8];
    const float* whh  = (const float*)d_in[9];
    const float* bih  = (const float*)d_in[10];
    const float* bhh  = (const float*)d_in[11];
    float* out = (float*)d_out;

    int N = in_sizes[0] / HH;   // 50000
    int E = in_sizes[2];        // 800000

    k_zero<<<2048, 256>>>();
    k_transpose<<<(HH * 3 * HH + 255) / 256, 256>>>(wih, whh);
    k_hist<<<(E + 255) / 256, 256>>>(et, E);
    k_scan<<<1, 1>>>();
    k_scatter<<<(E + 255) / 256, 256>>>(et, E);

    int mlpGrid = (E + TILE_E - 1) / TILE_E + TT;
    k_mlp<<<mlpGrid, 256>>>(h, ei, ea, W1, b1, W2, b2, E);

    k_gru<<<(N + 15) / 16, 256>>>(h, bih, bhh, out, N);
}